// round 15
// baseline (speedup 1.0000x reference)
#include <cuda_runtime.h>
#include <math.h>

#define NB 128
#define LXD 512
#define DD 32
#define KK 63
#define FF 2016   // KK*DD

// W3 pre-tiled and pre-scaled by log2(e): g_W3S[r][jj][fl], jj=63 row = b3.
// Logits come out as z*log2e -> exp2f(acc) == exp(z).
__device__ float g_W3S[32 * 64 * 64];

__global__ void prep_w3(const float* __restrict__ W3, const float* __restrict__ b3) {
    const float LOG2E = 1.4426950408889634f;
    int idx = blockIdx.x * blockDim.x + threadIdx.x;
    if (idx >= 32 * 64 * 64) return;
    int fl = idx & 63, jj = (idx >> 6) & 63, r = idx >> 12;
    int f = r * 64 + fl;
    float v = 0.f;
    if (f < FF) v = ((jj < KK) ? W3[jj * FF + f] : b3[f]) * LOG2E;
    g_W3S[idx] = v;
}

// SMEM layout (floats) — 56384 floats = 225536 bytes
#define OFF_X    0          // Xs  [512][32] = 16384 (compacted rows)
#define OFF_H    16384      // Hst [64][516] = 33024 (row 63 = ones)
#define OFF_W    49408      // Wt  [64][68]  = 4352
#define OFF_R1   53760      // [16][64]
#define OFF_R2   54784      // [16][64]
#define OFF_OS   55808      // 64
#define OFF_PERM 55872      // 512 (ints)
#define SMEM_FLOATS 56384

// Interleaved Phase-C pass: thread's rows are lt + 64*i, i = 0..RPG-1.
// All 64 groups active and balanced to within one row for Lm <= 64*RPG.
template<int RPG>
__device__ __forceinline__ void phaseC_il(
    const float* __restrict__ Hs, const float* __restrict__ Ws,
    const float* __restrict__ Xs, int lt, int g, int gq4, int Lm,
    float Sp[8], float Ap[8])
{
    float acc[RPG][8];
    #pragma unroll
    for (int i = 0; i < RPG; i++)
        #pragma unroll
        for (int fi = 0; fi < 8; fi++) acc[i][fi] = 0.f;

    #pragma unroll 8
    for (int j = 0; j < 64; ++j) {          // j=63 ones-row adds b3*log2e
        float h[RPG];
        #pragma unroll
        for (int i = 0; i < RPG; i++) h[i] = Hs[j * 516 + lt + 64 * i];
        float4 w0 = *(const float4*)&Ws[j * 68 + g * 8];
        float4 w1 = *(const float4*)&Ws[j * 68 + g * 8 + 4];
        float w[8] = {w0.x, w0.y, w0.z, w0.w, w1.x, w1.y, w1.z, w1.w};
        #pragma unroll
        for (int i = 0; i < RPG; i++)
            #pragma unroll
            for (int fi = 0; fi < 8; fi++) acc[i][fi] += h[i] * w[fi];
    }
    #pragma unroll
    for (int i = 0; i < RPG; i++) {
        int row = lt + 64 * i;
        if (row < Lm) {                     // guard: garbage H/X never reaches sums
            float4 x0 = *(const float4*)&Xs[row * 32 + gq4];
            float4 x1 = *(const float4*)&Xs[row * 32 + gq4 + 4];
            float x8[8] = {x0.x, x0.y, x0.z, x0.w, x1.x, x1.y, x1.z, x1.w};
            #pragma unroll
            for (int fi = 0; fi < 8; fi++) {
                float e = exp2f(acc[i][fi]);
                Sp[fi] += e;
                Ap[fi] += e * x8[fi];       // d = 8*(g&3) + fi
            }
        }
    }
}

__global__ __launch_bounds__(512, 1)
void ttcn_main(const float* __restrict__ Xg, const float* __restrict__ Mg,
               const float* __restrict__ W1g, const float* __restrict__ b1g,
               const float* __restrict__ W2g, const float* __restrict__ b2g,
               const float* __restrict__ Tb,  float* __restrict__ Og)
{
    extern __shared__ float sm[];
    float* Xs = sm + OFF_X;
    float* Hs = sm + OFF_H;
    float* Ws = sm + OFF_W;
    float* R1 = sm + OFF_R1;
    float* R2 = sm + OFF_R2;
    float* OS = sm + OFF_OS;
    int*   Pm = (int*)(sm + OFF_PERM);

    const int n    = blockIdx.x;
    const int t    = threadIdx.x;
    const int g    = t & 7;       // feature sub-group: owns f_local = g*8..g*8+7
    const int lt   = t >> 3;      // slot-group (0..63)
    const int warp = t >> 5;
    const int lane = t & 31;
    const int l08  = lt * 8;      // Phase A/B row base (8-row tiles)
    const int gq4  = (g & 3) * 8; // d-segment base for pooling

    // ---------- mask compaction: ballot + prefix scan over l ----------
    int m_i = (Mg[n * LXD + t] > 0.5f) ? 1 : 0;
    unsigned bal = __ballot_sync(0xffffffffu, m_i);
    if (lane == 0) ((int*)R1)[warp] = __popc(bal);
    __syncthreads();
    int base = 0, Lm = 0;
    #pragma unroll
    for (int w = 0; w < 16; w++) {
        int c = ((int*)R1)[w];
        if (w < warp) base += c;
        Lm += c;
    }
    if (m_i) Pm[base + __popc(bal & ((1u << lane) - 1u))] = t;
    __syncthreads();
    const int Lm_pad8 = (Lm + 7) & ~7;
    const bool act8   = (l08 < Lm_pad8);                   // Phase A/B activity

    // ---------- stage compacted X (zero pad to Lm_pad8) + W1 + ones-row + OS ----------
    {
        const float4* X4 = (const float4*)(Xg + (size_t)n * (LXD * DD));
        float4* Xs4 = (float4*)Xs;
        for (int idx = t; idx < Lm_pad8 * 8; idx += 512) {
            int s = idx >> 3, q = idx & 7;
            float4 v = make_float4(0.f, 0.f, 0.f, 0.f);
            if (s < Lm) v = X4[Pm[s] * 8 + q];
            Xs4[s * 8 + q] = v;
        }
        for (int idx = t; idx < 32 * 64; idx += 512) {
            int d = idx >> 6, j = idx & 63;
            Ws[d * 68 + j] = (j < KK) ? W1g[d * KK + j] : 0.f;
        }
        Hs[63 * 516 + t] = 1.f;      // ones row (b3 folding in Phase C)
        if (t < 64) OS[t] = 0.f;
    }
    float b1r[8], b2r[8];
    #pragma unroll
    for (int fi = 0; fi < 8; fi++) {
        int j = g * 8 + fi;
        b1r[fi] = (j < KK) ? b1g[j] : 0.f;
        b2r[fi] = (j < KK) ? b2g[j] : 0.f;
    }
    __syncthreads();

    // ---------- Phase A: H1 = relu(Xc @ W1 + b1) -> Hst rows 0..62 ----------
    {
        float acc[8][8];
        #pragma unroll
        for (int i = 0; i < 8; i++)
            #pragma unroll
            for (int fi = 0; fi < 8; fi++) acc[i][fi] = 0.f;

        if (act8) {
            #pragma unroll 4
            for (int d = 0; d < 32; ++d) {
                float h[8];
                #pragma unroll
                for (int i = 0; i < 8; i++) h[i] = Xs[(l08 + i) * 32 + d];
                float4 w0 = *(const float4*)&Ws[d * 68 + g * 8];
                float4 w1 = *(const float4*)&Ws[d * 68 + g * 8 + 4];
                float w[8] = {w0.x, w0.y, w0.z, w0.w, w1.x, w1.y, w1.z, w1.w};
                #pragma unroll
                for (int i = 0; i < 8; i++)
                    #pragma unroll
                    for (int fi = 0; fi < 8; fi++) acc[i][fi] += h[i] * w[fi];
            }
        }
        __syncthreads();   // all W1 reads done before Ws overwritten

        if (act8) {
            #pragma unroll
            for (int fi = 0; fi < 8; fi++) {
                int j = g * 8 + fi;
                if (j < KK) {
                    float4 v0, v1;
                    v0.x = fmaxf(acc[0][fi] + b1r[fi], 0.f);
                    v0.y = fmaxf(acc[1][fi] + b1r[fi], 0.f);
                    v0.z = fmaxf(acc[2][fi] + b1r[fi], 0.f);
                    v0.w = fmaxf(acc[3][fi] + b1r[fi], 0.f);
                    v1.x = fmaxf(acc[4][fi] + b1r[fi], 0.f);
                    v1.y = fmaxf(acc[5][fi] + b1r[fi], 0.f);
                    v1.z = fmaxf(acc[6][fi] + b1r[fi], 0.f);
                    v1.w = fmaxf(acc[7][fi] + b1r[fi], 0.f);
                    *(float4*)&Hs[j * 516 + l08]     = v0;
                    *(float4*)&Hs[j * 516 + l08 + 4] = v1;
                }
            }
        }
        for (int idx = t; idx < KK * 64; idx += 512) {
            int m = idx >> 6, col = idx & 63;
            Ws[m * 68 + col] = (col < KK) ? W2g[m * KK + col] : 0.f;
        }
    }
    __syncthreads();

    // ---------- Phase B: H2 = relu(H1 @ W2 + b2), in place ----------
    {
        float acc[8][8];
        #pragma unroll
        for (int i = 0; i < 8; i++)
            #pragma unroll
            for (int fi = 0; fi < 8; fi++) acc[i][fi] = 0.f;

        if (act8) {
            #pragma unroll 7
            for (int m = 0; m < KK; ++m) {
                float4 a0 = *(const float4*)&Hs[m * 516 + l08];
                float4 a1 = *(const float4*)&Hs[m * 516 + l08 + 4];
                float4 w0 = *(const float4*)&Ws[m * 68 + g * 8];
                float4 w1 = *(const float4*)&Ws[m * 68 + g * 8 + 4];
                float h[8] = {a0.x, a0.y, a0.z, a0.w, a1.x, a1.y, a1.z, a1.w};
                float w[8] = {w0.x, w0.y, w0.z, w0.w, w1.x, w1.y, w1.z, w1.w};
                #pragma unroll
                for (int i = 0; i < 8; i++)
                    #pragma unroll
                    for (int fi = 0; fi < 8; fi++) acc[i][fi] += h[i] * w[fi];
            }
        }
        __syncwarp();   // orders reads before in-place writes (same-warp readers)
        if (act8) {
            #pragma unroll
            for (int fi = 0; fi < 8; fi++) {
                int j = g * 8 + fi;
                if (j < KK) {
                    float4 v0, v1;
                    v0.x = fmaxf(acc[0][fi] + b2r[fi], 0.f);
                    v0.y = fmaxf(acc[1][fi] + b2r[fi], 0.f);
                    v0.z = fmaxf(acc[2][fi] + b2r[fi], 0.f);
                    v0.w = fmaxf(acc[3][fi] + b2r[fi], 0.f);
                    v1.x = fmaxf(acc[4][fi] + b2r[fi], 0.f);
                    v1.y = fmaxf(acc[5][fi] + b2r[fi], 0.f);
                    v1.z = fmaxf(acc[6][fi] + b2r[fi], 0.f);
                    v1.w = fmaxf(acc[7][fi] + b2r[fi], 0.f);
                    *(float4*)&Hs[j * 516 + l08]     = v0;
                    *(float4*)&Hs[j * 516 + l08 + 4] = v1;
                }
            }
        }
    }
    __syncthreads();   // W2 reads done before Phase C stages W3 tile 0

    // ---------- Phase C: interleaved balanced rows + W3 register double-buffer ----------
    // prologue: stage tile r=0
    {
        const float4* src = (const float4*)(g_W3S);
        #pragma unroll 2
        for (int idx = t; idx < 1024; idx += 512) {
            int jj = idx >> 4, q = idx & 15;
            *(float4*)&Ws[jj * 68 + q * 4] = src[idx];
        }
    }
    const int pf_jj0 = t >> 4,          pf_q0 = t & 15;          // idx = t
    const int pf_jj1 = (t + 512) >> 4,  pf_q1 = t & 15;          // idx = t+512

    for (int r = 0; r < 32; ++r) {
        __syncthreads();   // Ws tile r visible (and R reads from prev round done)

        float Sp[8], Ap[8];
        #pragma unroll
        for (int fi = 0; fi < 8; fi++) { Sp[fi] = 0.f; Ap[fi] = 0.f; }

        if (Lm <= 256) {
            phaseC_il<4>(Hs, Ws, Xs, lt, g, gq4, Lm, Sp, Ap);
        } else if (Lm <= 320) {
            phaseC_il<5>(Hs, Ws, Xs, lt, g, gq4, Lm, Sp, Ap);
        } else {
            // generic fallback (any Lm): strided 5-row blocks
            for (int b = lt * 5; b < Lm; b += 320) {
                float acc[5][8];
                #pragma unroll
                for (int i = 0; i < 5; i++)
                    #pragma unroll
                    for (int fi = 0; fi < 8; fi++) acc[i][fi] = 0.f;
                #pragma unroll 8
                for (int j = 0; j < 64; ++j) {
                    const float* hp = &Hs[j * 516 + b];
                    float h[5];
                    #pragma unroll
                    for (int i = 0; i < 5; i++) h[i] = hp[i];
                    float4 w0 = *(const float4*)&Ws[j * 68 + g * 8];
                    float4 w1 = *(const float4*)&Ws[j * 68 + g * 8 + 4];
                    float w[8] = {w0.x, w0.y, w0.z, w0.w, w1.x, w1.y, w1.z, w1.w};
                    #pragma unroll
                    for (int i = 0; i < 5; i++)
                        #pragma unroll
                        for (int fi = 0; fi < 8; fi++) acc[i][fi] += h[i] * w[fi];
                }
                #pragma unroll
                for (int i = 0; i < 5; i++) {
                    if (b + i < Lm) {
                        float4 x0 = *(const float4*)&Xs[(b + i) * 32 + gq4];
                        float4 x1 = *(const float4*)&Xs[(b + i) * 32 + gq4 + 4];
                        float x8[8] = {x0.x, x0.y, x0.z, x0.w, x1.x, x1.y, x1.z, x1.w};
                        #pragma unroll
                        for (int fi = 0; fi < 8; fi++) {
                            float e = exp2f(acc[i][fi]);
                            Sp[fi] += e;
                            Ap[fi] += e * x8[fi];
                        }
                    }
                }
            }
        }

        // prefetch next W3 tile into registers (LDG hidden behind reduction)
        float4 pf0, pf1;
        if (r + 1 < 32) {
            const float4* src = (const float4*)(g_W3S + (r + 1) * 4096);
            pf0 = src[t];
            pf1 = src[t + 512];
        }

        #pragma unroll
        for (int fi = 0; fi < 8; fi++) {
            Sp[fi] += __shfl_xor_sync(0xffffffffu, Sp[fi], 8);
            Sp[fi] += __shfl_xor_sync(0xffffffffu, Sp[fi], 16);
            Ap[fi] += __shfl_xor_sync(0xffffffffu, Ap[fi], 8);
            Ap[fi] += __shfl_xor_sync(0xffffffffu, Ap[fi], 16);
        }
        if (lane < 8) {
            float4 s0 = {Sp[0], Sp[1], Sp[2], Sp[3]};
            float4 s1 = {Sp[4], Sp[5], Sp[6], Sp[7]};
            float4 a0 = {Ap[0], Ap[1], Ap[2], Ap[3]};
            float4 a1 = {Ap[4], Ap[5], Ap[6], Ap[7]};
            *(float4*)&R1[warp * 64 + lane * 8]     = s0;
            *(float4*)&R1[warp * 64 + lane * 8 + 4] = s1;
            *(float4*)&R2[warp * 64 + lane * 8]     = a0;
            *(float4*)&R2[warp * 64 + lane * 8 + 4] = a1;
        }
        __syncthreads();   // R ready; also: all warps finished reading Ws tile r

        if (t < 64) {
            float S = 0.f, A = 0.f;
            #pragma unroll
            for (int w16 = 0; w16 < 16; w16++) {
                S += R1[w16 * 64 + t];
                A += R2[w16 * 64 + t];
            }
            int f = r * 64 + t;
            float gq = (f < FF) ? (A / S) : 0.f;
            gq += __shfl_down_sync(0xffffffffu, gq, 16);
            gq += __shfl_down_sync(0xffffffffu, gq, 8);
            gq += __shfl_down_sync(0xffffffffu, gq, 4);
            gq += __shfl_down_sync(0xffffffffu, gq, 2);
            gq += __shfl_down_sync(0xffffffffu, gq, 1);
            if (lane == 0) OS[2 * r + warp] = gq;   // k = 2r + warp
        }
        // store prefetched tile (safe: everyone is past the GEMM of tile r)
        if (r + 1 < 32) {
            *(float4*)&Ws[pf_jj0 * 68 + pf_q0 * 4] = pf0;
            *(float4*)&Ws[pf_jj1 * 68 + pf_q1 * 4] = pf1;
        }
    }
    __syncthreads();

    if (t < KK) Og[n * KK + t] = fmaxf(OS[t] + Tb[t], 0.f);
}

extern "C" void kernel_launch(void* const* d_in, const int* in_sizes, int n_in,
                              void* d_out, int out_size) {
    const float* X  = (const float*)d_in[0];
    const float* M  = (const float*)d_in[1];
    const float* W1 = (const float*)d_in[2];
    const float* b1 = (const float*)d_in[3];
    const float* W2 = (const float*)d_in[4];
    const float* b2 = (const float*)d_in[5];
    const float* W3 = (const float*)d_in[6];
    const float* b3 = (const float*)d_in[7];
    const float* Tb = (const float*)d_in[8];
    float* Og = (float*)d_out;

    prep_w3<<<(32 * 64 * 64 + 255) / 256, 256>>>(W3, b3);

    size_t smem = (size_t)SMEM_FLOATS * sizeof(float);
    cudaFuncSetAttribute(ttcn_main, cudaFuncAttributeMaxDynamicSharedMemorySize, (int)smem);
    ttcn_main<<<NB, 512, smem>>>(X, M, W1, b1, W2, b2, Tb, Og);
}